// round 2
// baseline (speedup 1.0000x reference)
#include <cuda_runtime.h>
#include <math.h>

// Problem constants
constexpr int cB = 2, cT = 2048, cS = 2048, cD = 1024, cH = 16, cDK = 64;
constexpr int cHD = cH * cDK;      // 1024
constexpr int cMT = cB * cT;       // 4096 rows for the projection GEMMs

// Scratch (alloc-free rule: __device__ globals)
__device__ float g_q[(size_t)cMT * cHD];
__device__ float g_k[(size_t)cB * cS * cHD];
__device__ float g_v[(size_t)cB * cS * cHD];
__device__ float g_attn[(size_t)cMT * cHD];

// ---------------------------------------------------------------------------
// GEMM: C[M,N] = (X[M,K] @ W[K,N] + bias[N]) * scale
// Tile 64x64x16, 256 threads, 4x4 per thread.
// ---------------------------------------------------------------------------
constexpr int GBM = 64, GBN = 64, GBK = 16;

__global__ __launch_bounds__(256) void gemm_bias(
    const float* __restrict__ X, const float* __restrict__ W,
    const float* __restrict__ bias, float* __restrict__ C,
    int M, int N, int K, float scale)
{
    __shared__ float Xs[GBM * GBK];   // [m][k]  (A reads are broadcast)
    __shared__ float Ws[GBK * GBN];   // [k][n]  (B reads are LDS.128)

    const int tid = threadIdx.x;
    const int tx = tid & 15;          // n-group
    const int ty = tid >> 4;          // m-group
    const int m0 = blockIdx.y * GBM;
    const int n0 = blockIdx.x * GBN;

    float acc[4][4] = {};

    for (int k0 = 0; k0 < K; k0 += GBK) {
        // X tile 64x16: thread loads one float4; STS is perfectly linear
        {
            const int r = tid >> 2, c = (tid & 3) << 2;
            const float4 v = *reinterpret_cast<const float4*>(
                X + (size_t)(m0 + r) * K + k0 + c);
            *reinterpret_cast<float4*>(&Xs[r * GBK + c]) = v;
        }
        // W tile 16x64
        {
            const int r = tid >> 4, c = (tid & 15) << 2;
            const float4 v = *reinterpret_cast<const float4*>(
                W + (size_t)(k0 + r) * N + n0 + c);
            *reinterpret_cast<float4*>(&Ws[r * GBN + c]) = v;
        }
        __syncthreads();

        #pragma unroll
        for (int kk = 0; kk < GBK; kk++) {
            const float a0 = Xs[(ty * 4 + 0) * GBK + kk];
            const float a1 = Xs[(ty * 4 + 1) * GBK + kk];
            const float a2 = Xs[(ty * 4 + 2) * GBK + kk];
            const float a3 = Xs[(ty * 4 + 3) * GBK + kk];
            const float4 bb = *reinterpret_cast<const float4*>(&Ws[kk * GBN + (tx << 2)]);
            acc[0][0] += a0 * bb.x; acc[0][1] += a0 * bb.y; acc[0][2] += a0 * bb.z; acc[0][3] += a0 * bb.w;
            acc[1][0] += a1 * bb.x; acc[1][1] += a1 * bb.y; acc[1][2] += a1 * bb.z; acc[1][3] += a1 * bb.w;
            acc[2][0] += a2 * bb.x; acc[2][1] += a2 * bb.y; acc[2][2] += a2 * bb.z; acc[2][3] += a2 * bb.w;
            acc[3][0] += a3 * bb.x; acc[3][1] += a3 * bb.y; acc[3][2] += a3 * bb.z; acc[3][3] += a3 * bb.w;
        }
        __syncthreads();
    }

    const float4 bv = *reinterpret_cast<const float4*>(&bias[n0 + (tx << 2)]);
    #pragma unroll
    for (int i = 0; i < 4; i++) {
        float4 o;
        o.x = (acc[i][0] + bv.x) * scale;
        o.y = (acc[i][1] + bv.y) * scale;
        o.z = (acc[i][2] + bv.z) * scale;
        o.w = (acc[i][3] + bv.w) * scale;
        *reinterpret_cast<float4*>(
            &C[(size_t)(m0 + ty * 4 + i) * N + n0 + (tx << 2)]) = o;
    }
}

// ---------------------------------------------------------------------------
// Flash attention: per block = (t-tile of 64, head, batch). 256 threads,
// 8 warps; each warp owns 8 query rows. Online softmax over s-tiles of 64.
// K tile stored transposed with 16B-granular XOR swizzle to keep the
// transpose STS at <=2-way conflicts while reads stay aligned LDS.128.
// ---------------------------------------------------------------------------
constexpr int ATTN_SMEM_BYTES = 4 * 64 * 64 * 4;   // qs + kts + vs + ps = 64KB

__global__ __launch_bounds__(256) void attn_kernel(
    const float* __restrict__ Qg, const float* __restrict__ Kg,
    const float* __restrict__ Vg, float* __restrict__ Og)
{
    extern __shared__ float sm[];
    float* qs  = sm;                 // [t][dk]   (broadcast A reads)
    float* kts = sm + 4096;          // swizzled [dk][s]
    float* vs  = sm + 8192;          // [s][dk]
    float* ps  = sm + 12288;         // [t][s]    (warp-private rows)

    const int tid = threadIdx.x;
    const int tx = tid & 15;         // 4-col group (s for QK, dk for PV)
    const int ty = tid >> 4;         // 4-row group (t)
    const int t0 = blockIdx.x * 64;
    const int hi = blockIdx.y;
    const int bi = blockIdx.z;

    // Load Q tile (64 rows x 64 dk)
    #pragma unroll
    for (int it = 0; it < 4; it++) {
        const int idx = tid + it * 256;          // float4 units
        const int r = idx >> 4;
        const int c = (idx & 15) << 2;
        const float4 v = *reinterpret_cast<const float4*>(
            Qg + ((size_t)(bi * cT + t0 + r) * cH + hi) * cDK + c);
        *reinterpret_cast<float4*>(&qs[r * 64 + c]) = v;
    }

    float acc[4][4] = {};
    float m[4], l[4];
    #pragma unroll
    for (int i = 0; i < 4; i++) { m[i] = -INFINITY; l[i] = 0.0f; }

    for (int s0 = 0; s0 < cS; s0 += 64) {
        __syncthreads();
        // K tile -> transposed + swizzled; V tile -> natural layout
        #pragma unroll
        for (int it = 0; it < 4; it++) {
            const int idx = tid + it * 256;
            const int r = idx >> 4;              // s local
            const int c = (idx & 15) << 2;       // dk base
            const float4 kv = *reinterpret_cast<const float4*>(
                Kg + ((size_t)(bi * cS + s0 + r) * cH + hi) * cDK + c);
            const int col16 = (((r >> 2) ^ (c >> 2)) & 15) << 2;
            const int base = col16 + (r & 3);
            kts[(c + 0) * 64 + base] = kv.x;
            kts[(c + 1) * 64 + base] = kv.y;
            kts[(c + 2) * 64 + base] = kv.z;
            kts[(c + 3) * 64 + base] = kv.w;
            const float4 vv = *reinterpret_cast<const float4*>(
                Vg + ((size_t)(bi * cS + s0 + r) * cH + hi) * cDK + c);
            *reinterpret_cast<float4*>(&vs[r * 64 + c]) = vv;
        }
        __syncthreads();

        // S = Q @ K^T  (64x64x64)
        float sacc[4][4] = {};
        #pragma unroll 16
        for (int kk = 0; kk < 64; kk++) {
            const float a0 = qs[(ty * 4 + 0) * 64 + kk];
            const float a1 = qs[(ty * 4 + 1) * 64 + kk];
            const float a2 = qs[(ty * 4 + 2) * 64 + kk];
            const float a3 = qs[(ty * 4 + 3) * 64 + kk];
            const float4 bb = *reinterpret_cast<const float4*>(
                &kts[kk * 64 + (((tx ^ (kk >> 2)) & 15) << 2)]);
            sacc[0][0] += a0 * bb.x; sacc[0][1] += a0 * bb.y; sacc[0][2] += a0 * bb.z; sacc[0][3] += a0 * bb.w;
            sacc[1][0] += a1 * bb.x; sacc[1][1] += a1 * bb.y; sacc[1][2] += a1 * bb.z; sacc[1][3] += a1 * bb.w;
            sacc[2][0] += a2 * bb.x; sacc[2][1] += a2 * bb.y; sacc[2][2] += a2 * bb.z; sacc[2][3] += a2 * bb.w;
            sacc[3][0] += a3 * bb.x; sacc[3][1] += a3 * bb.y; sacc[3][2] += a3 * bb.z; sacc[3][3] += a3 * bb.w;
        }

        // Online softmax per row (row owned by a 16-lane half-warp)
        #pragma unroll
        for (int i = 0; i < 4; i++) {
            float mt = fmaxf(fmaxf(sacc[i][0], sacc[i][1]),
                             fmaxf(sacc[i][2], sacc[i][3]));
            #pragma unroll
            for (int off = 8; off >= 1; off >>= 1)
                mt = fmaxf(mt, __shfl_xor_sync(0xffffffffu, mt, off));
            const float mnew = fmaxf(m[i], mt);
            const float corr = __expf(m[i] - mnew);
            const float p0 = __expf(sacc[i][0] - mnew);
            const float p1 = __expf(sacc[i][1] - mnew);
            const float p2 = __expf(sacc[i][2] - mnew);
            const float p3 = __expf(sacc[i][3] - mnew);
            float ls = (p0 + p1) + (p2 + p3);
            #pragma unroll
            for (int off = 8; off >= 1; off >>= 1)
                ls += __shfl_xor_sync(0xffffffffu, ls, off);
            l[i] = l[i] * corr + ls;
            m[i] = mnew;
            acc[i][0] *= corr; acc[i][1] *= corr;
            acc[i][2] *= corr; acc[i][3] *= corr;
            *reinterpret_cast<float4*>(&ps[(ty * 4 + i) * 64 + (tx << 2)]) =
                make_float4(p0, p1, p2, p3);
        }
        __syncwarp();

        // O += P @ V  (64x64x64)
        #pragma unroll 16
        for (int kk = 0; kk < 64; kk++) {
            const float a0 = ps[(ty * 4 + 0) * 64 + kk];
            const float a1 = ps[(ty * 4 + 1) * 64 + kk];
            const float a2 = ps[(ty * 4 + 2) * 64 + kk];
            const float a3 = ps[(ty * 4 + 3) * 64 + kk];
            const float4 bb = *reinterpret_cast<const float4*>(&vs[kk * 64 + (tx << 2)]);
            acc[0][0] += a0 * bb.x; acc[0][1] += a0 * bb.y; acc[0][2] += a0 * bb.z; acc[0][3] += a0 * bb.w;
            acc[1][0] += a1 * bb.x; acc[1][1] += a1 * bb.y; acc[1][2] += a1 * bb.z; acc[1][3] += a1 * bb.w;
            acc[2][0] += a2 * bb.x; acc[2][1] += a2 * bb.y; acc[2][2] += a2 * bb.z; acc[2][3] += a2 * bb.w;
            acc[3][0] += a3 * bb.x; acc[3][1] += a3 * bb.y; acc[3][2] += a3 * bb.z; acc[3][3] += a3 * bb.w;
        }
    }

    // Normalize and store attn output [B,T,H,DK]
    #pragma unroll
    for (int i = 0; i < 4; i++) {
        const float inv = 1.0f / l[i];
        float4 o;
        o.x = acc[i][0] * inv; o.y = acc[i][1] * inv;
        o.z = acc[i][2] * inv; o.w = acc[i][3] * inv;
        *reinterpret_cast<float4*>(
            &Og[((size_t)(bi * cT + t0 + ty * 4 + i) * cH + hi) * cDK + (tx << 2)]) = o;
    }
}

// ---------------------------------------------------------------------------
extern "C" void kernel_launch(void* const* d_in, const int* in_sizes, int n_in,
                              void* d_out, int out_size)
{
    const float* query = (const float*)d_in[0];
    const float* value = (const float*)d_in[1];
    const float* key   = (const float*)d_in[2];
    const float* Wq    = (const float*)d_in[3];
    const float* bq    = (const float*)d_in[4];
    const float* Wk    = (const float*)d_in[5];
    const float* bk    = (const float*)d_in[6];
    const float* Wv    = (const float*)d_in[7];
    const float* bv    = (const float*)d_in[8];
    const float* Wo    = (const float*)d_in[9];
    const float* bo    = (const float*)d_in[10];
    float* out = (float*)d_out;

    float *pq, *pk, *pv, *pa;
    cudaGetSymbolAddress((void**)&pq, g_q);
    cudaGetSymbolAddress((void**)&pk, g_k);
    cudaGetSymbolAddress((void**)&pv, g_v);
    cudaGetSymbolAddress((void**)&pa, g_attn);

    cudaFuncSetAttribute(attn_kernel,
                         cudaFuncAttributeMaxDynamicSharedMemorySize,
                         ATTN_SMEM_BYTES);

    const dim3 gg(cHD / GBN, cMT / GBM);   // (16, 64)
    const float qscale = 0.125f;           // 1/sqrt(DK), exact in fp32

    gemm_bias<<<gg, 256>>>(query, Wq, bq, pq, cMT, cHD, cD, qscale);
    gemm_bias<<<gg, 256>>>(key,   Wk, bk, pk, cMT, cHD, cD, 1.0f);
    gemm_bias<<<gg, 256>>>(value, Wv, bv, pv, cMT, cHD, cD, 1.0f);

    attn_kernel<<<dim3(cT / 64, cH, cB), 256, ATTN_SMEM_BYTES>>>(pq, pk, pv, pa);

    gemm_bias<<<gg, 256>>>(pa, Wo, bo, out, cMT, cD, cHD, 1.0f);
}